// round 11
// baseline (speedup 1.0000x reference)
#include <cuda_runtime.h>
#include <cuda_fp16.h>
#include <cstdint>
#include <math.h>

// ----------------------------------------------------------------------------
// BahdanauAttentionAudio — HMMA fp16 single-term score GEMM (tile-persistent)
//   B=32, T=2048, H=1024, U=1024, KN=32
// Output layout: [ ctx (32*1024) | att (32*2048) | score (32*2048) ]
// ----------------------------------------------------------------------------

#define B_   32
#define T_   2048
#define H_   1024
#define U_   1024
#define KN_  32
#define TAPS 31
#define NCH  17            // 16 chunks of H (K=64) + 1 loc chunk (K=32, zero-padded)
#define NT   4             // t-tiles per score CTA
#define NCC  (NT * NCH)    // 68 continuous chunks per CTA

// packed format: per (chunk c, row r): 128 bytes = 64 fp16 (k = c*64 .. +63)
// granule g (8 fp16 = 16B) stored at byte offset ((g ^ (r & 7)) * 16)
__device__ __align__(128) uint4 g_vpk[(size_t)B_ * NCH * T_ * 8];   // [b][c][t][8]
__device__ __align__(128) uint4 g_wpk[(size_t)NCH * U_ * 8];        // [c][u][8]
__device__ __align__(16)  float g_qproj[B_ * U_];
__device__ __align__(16)  float g_part[8 * B_ * T_];
__device__ __align__(16)  float g_ctx_partial[B_ * 32 * H_];

// ---------------- helpers ----------------------------------------------------
__device__ __forceinline__ uint32_t smem_to_u32(const void* p) {
    uint32_t a;
    asm("{ .reg .u64 t; cvta.to.shared.u64 t, %1; cvt.u32.u64 %0, t; }"
        : "=r"(a) : "l"(p));
    return a;
}

__device__ __forceinline__ uint32_t pkh(float a, float b) {
    __half2 h = __floats2half2_rn(a, b);
    return *reinterpret_cast<uint32_t*>(&h);
}

__device__ __forceinline__ uint4 pk8(const float* f) {
    uint4 r;
    r.x = pkh(f[0], f[1]); r.y = pkh(f[2], f[3]);
    r.z = pkh(f[4], f[5]); r.w = pkh(f[6], f[7]);
    return r;
}

__device__ __forceinline__ float fast_tanh(float x) {
    float xx = fminf(fmaxf(x, -15.f), 15.f) * 2.8853900817779268f;
    float e, r;
    asm("ex2.approx.f32 %0, %1;" : "=f"(e) : "f"(xx));
    float d = e + 1.f;
    asm("rcp.approx.f32 %0, %1;" : "=f"(r) : "f"(d));
    return (e - 1.f) * r;
}

#define MBARRIER_INIT(m, c) \
    asm volatile("mbarrier.init.shared.b64 [%0], %1;" \
                 :: "r"((uint32_t)(m)), "r"((uint32_t)(c)) : "memory")
#define MBARRIER_EXPECT_TX(m, n) \
    asm volatile("mbarrier.arrive.expect_tx.shared.b64 _, [%0], %1;" \
                 :: "r"((uint32_t)(m)), "r"((uint32_t)(n)) : "memory")
#define MBARRIER_ARRIVE(m) \
    asm volatile("mbarrier.arrive.shared.b64 _, [%0];" \
                 :: "r"((uint32_t)(m)) : "memory")

#define MBARRIER_WAIT_PARITY(mb, pp) do {                                     \
    uint32_t _m = (uint32_t)(mb), _p = (uint32_t)(pp), _d;                    \
    asm volatile(                                                             \
        "{\n\t.reg .pred p;\n\t"                                              \
        "mbarrier.try_wait.parity.acquire.cta.shared::cta.b64 p, [%1], %2;\n\t" \
        "selp.b32 %0, 1, 0, p;\n\t}"                                          \
        : "=r"(_d) : "r"(_m), "r"(_p) : "memory");                            \
    if (!_d) {                                                                \
        asm volatile(                                                         \
            "{\n\t.reg .pred P1;\n\t"                                         \
            "WL_%=:\n\t"                                                      \
            "mbarrier.try_wait.parity.acquire.cta.shared::cta.b64 P1, [%0], %1, 0x989680;\n\t" \
            "@P1 bra.uni WD_%=;\n\t"                                          \
            "bra.uni WL_%=;\n\t"                                              \
            "WD_%=:\n\t}"                                                     \
            :: "r"(_m), "r"(_p) : "memory");                                  \
    }                                                                         \
} while (0)

__device__ __forceinline__ void bulk_g2s(uint32_t dst, const void* src,
                                         uint32_t bytes, uint32_t mbar) {
    asm volatile(
        "cp.async.bulk.shared::cluster.global.mbarrier::complete_tx::bytes "
        "[%0], [%1], %2, [%3];"
        :: "r"(dst), "l"(src), "r"(bytes), "r"(mbar) : "memory");
}

__device__ __forceinline__ void ldsm4(uint32_t (&r)[4], uint32_t a) {
    asm volatile("ldmatrix.sync.aligned.m8n8.x4.shared.b16 {%0,%1,%2,%3}, [%4];"
                 : "=r"(r[0]), "=r"(r[1]), "=r"(r[2]), "=r"(r[3]) : "r"(a));
}

__device__ __forceinline__ void mma16816(float* c, const uint32_t* a,
                                         const uint32_t* b) {
    asm volatile(
        "mma.sync.aligned.m16n8k16.row.col.f32.f16.f16.f32 "
        "{%0,%1,%2,%3}, {%4,%5,%6,%7}, {%8,%9}, {%0,%1,%2,%3};"
        : "+f"(c[0]), "+f"(c[1]), "+f"(c[2]), "+f"(c[3])
        : "r"(a[0]), "r"(a[1]), "r"(a[2]), "r"(a[3]), "r"(b[0]), "r"(b[1]));
}

// ---------------- 1) query projection ----------------------------------------
__global__ void qproj_kernel(const float* __restrict__ query,
                             const float* __restrict__ W2w,
                             const float* __restrict__ W1b,
                             const float* __restrict__ W2b) {
    extern __shared__ float qs[];      // [32][1024]
    const int tid  = threadIdx.x;      // 256
    const int lane = tid & 31;
    const int wid  = tid >> 5;
    for (int i = tid; i < B_ * H_ / 4; i += 256)
        ((float4*)qs)[i] = ((const float4*)query)[i];
    __syncthreads();

    const int u = blockIdx.x * 8 + wid;
    const float* wrow = W2w + (size_t)u * H_;
    float w[32];
#pragma unroll
    for (int j = 0; j < 32; j++) w[j] = __ldg(&wrow[j * 32 + lane]);

    float bias = 0.f;
    if (lane == 0) bias = __ldg(&W1b[u]) + __ldg(&W2b[u]);

    for (int b = 0; b < B_; b++) {
        const float* qr = qs + b * H_;
        float acc = 0.f;
#pragma unroll
        for (int j = 0; j < 32; j++) acc += w[j] * qr[j * 32 + lane];
#pragma unroll
        for (int off = 16; off > 0; off >>= 1)
            acc += __shfl_xor_sync(0xffffffffu, acc, off);
        if (lane == 0) g_qproj[(size_t)b * U_ + u] = acc + bias;
    }
}

// ---------------- 2a) pack values (fp16, coalesced granule-per-thread) -------
__global__ void pack_values_kernel(const float* __restrict__ values) {
    int idx = blockIdx.x * 256 + threadIdx.x;
    int g = idx & 7;
    int t = (idx >> 3) & 2047;
    int c = (idx >> 14) & 15;
    int b = idx >> 18;
    const float4* src = (const float4*)(values +
        ((size_t)(b * 2048 + t) * 1024 + c * 64 + g * 8));
    float4 v0 = __ldg(src), v1 = __ldg(src + 1);
    float f[8] = {v0.x, v0.y, v0.z, v0.w, v1.x, v1.y, v1.z, v1.w};
    g_vpk[((size_t)((b * NCH + c) * 2048 + t) * 8) + (g ^ (t & 7))] = pk8(f);
}

// ---------------- 2b) pack W1_w (fp16) ----------------------------------------
__global__ void pack_w_kernel(const float* __restrict__ W1w) {
    int idx = blockIdx.x * 256 + threadIdx.x;   // c*1024 + u  (c 0..15)
    int u = idx & 1023;
    int c = idx >> 10;
    const float4* src = (const float4*)(W1w + ((size_t)u * 1024 + c * 64));
    uint4* dst = g_wpk + ((size_t)(c * U_ + u) * 8);
    int r = u & 7;
    float f[8];
#pragma unroll
    for (int g = 0; g < 8; g++) {
        float4 v0 = __ldg(src + g * 2), v1 = __ldg(src + g * 2 + 1);
        f[0] = v0.x; f[1] = v0.y; f[2] = v0.z; f[3] = v0.w;
        f[4] = v1.x; f[5] = v1.y; f[6] = v1.z; f[7] = v1.w;
        dst[g ^ r] = pk8(f);
    }
}

// ---------------- 2c) pack loc_proj_w (chunk 16 of W) -------------------------
__global__ void pack_lp_kernel(const float* __restrict__ LPw) {
    int u = blockIdx.x * 256 + threadIdx.x;     // 0..1023
    const float4* src = (const float4*)(LPw + (size_t)u * 32);
    uint4* dst = g_wpk + ((size_t)(16 * U_ + u) * 8);
    int r = u & 7;
    float f[8];
    uint4 z = make_uint4(0, 0, 0, 0);
#pragma unroll
    for (int g = 0; g < 4; g++) {
        float4 v0 = __ldg(src + g * 2), v1 = __ldg(src + g * 2 + 1);
        f[0] = v0.x; f[1] = v0.y; f[2] = v0.z; f[3] = v0.w;
        f[4] = v1.x; f[5] = v1.y; f[6] = v1.z; f[7] = v1.w;
        dst[g ^ r] = pk8(f);
    }
#pragma unroll
    for (int g = 4; g < 8; g++) dst[g ^ r] = z;
}

// ---------------- 2d) location conv + pack (chunk 16 of V) --------------------
__global__ void loc_pack_kernel(const float* __restrict__ prev_att,
                                const float* __restrict__ conv_w) {
    int b  = blockIdx.y;
    int t0 = blockIdx.x * 256;
    int tid = threadIdx.x;
    __shared__ float pa[256 + TAPS - 1];
    __shared__ float w[KN_][TAPS];
    for (int i = tid; i < 256 + TAPS - 1; i += 256) {
        int t = t0 - (TAPS / 2) + i;
        pa[i] = (t >= 0 && t < T_) ? prev_att[(size_t)b * T_ + t] : 0.f;
    }
    for (int i = tid; i < KN_ * TAPS; i += 256) w[i / TAPS][i % TAPS] = conv_w[i];
    __syncthreads();
    int t = t0 + tid;
    float a[KN_];
#pragma unroll 4
    for (int k = 0; k < KN_; k++) {
        float s = 0.f;
#pragma unroll
        for (int j = 0; j < TAPS; j++) s += w[k][j] * pa[tid + j];
        a[k] = s;
    }
    uint4* dst = g_vpk + ((size_t)((b * NCH + 16) * 2048 + t) * 8);
    int r = t & 7;
    uint4 z = make_uint4(0, 0, 0, 0);
#pragma unroll
    for (int g = 0; g < 4; g++) dst[g ^ r] = pk8(a + g * 8);
#pragma unroll
    for (int g = 4; g < 8; g++) dst[g ^ r] = z;
}

// ---------------- 3) score GEMM via mma.sync (tile-persistent) ----------------
// CTA: 256 t x 128 u tile, 512 threads, NT=4 tiles per CTA (t0 advances).
// Continuous chunk stream cc = 0..67 through a 4-stage 48KB pipeline; the
// producer runs ahead across tile boundaries so per-tile epilogues overlap
// with TMA prefetch of the next tile.
#define STG       49152
#define OFF_MBAR  196608     // 4 x full (TMA) barriers, 8B each
#define OFF_EMPTY 196640     // 4 x empty barriers, 8B each
#define OFF_QP    196672
#define OFF_VW    197184
#define OFF_RED   197696
#define SMEM_TOTAL 201792

__device__ __forceinline__ void issue_cc(uint32_t sb, int cc,
                                         int b, int t00, int u0) {
    const int s    = cc & 3;
    const int tile = cc / NCH;
    const int c    = cc - tile * NCH;
    uint32_t mbar = sb + OFF_MBAR + s * 8;
    MBARRIER_EXPECT_TX(mbar, 49152u);
    bulk_g2s(sb + s * STG,
             (const void*)(g_vpk + ((size_t)((b * NCH + c) * 2048 + t00 + tile * 256) * 8)),
             32768u, mbar);
    bulk_g2s(sb + s * STG + 32768,
             (const void*)(g_wpk + ((size_t)(c * U_ + u0) * 8)),
             16384u, mbar);
}

__global__ __launch_bounds__(512, 1)
void score_mma_kernel(const float* __restrict__ Vw) {
    extern __shared__ char smem[];
    const uint32_t sb = smem_to_u32(smem);
    const int tid  = threadIdx.x;
    const int lane = tid & 31;
    const int wid  = tid >> 5;
    const int ut  = blockIdx.x;         // 0..7 (fastest -> A L2 reuse)
    const int b   = blockIdx.y;         // 0..31
    const int tt2 = blockIdx.z;         // 0..1
    const int t00 = tt2 * 1024, u0 = ut * 128;

    if (tid == 0) {
#pragma unroll
        for (int s = 0; s < 4; s++) {
            MBARRIER_INIT(sb + OFF_MBAR + s * 8, 1);
            MBARRIER_INIT(sb + OFF_EMPTY + s * 8, 16);   // one arrive per warp
        }
    }
    __syncthreads();
    if (tid == 0) {
        for (int cc = 0; cc < 4; cc++) issue_cc(sb, cc, b, t00, u0);
    }

    float* qp = (float*)(smem + OFF_QP);
    float* vw = (float*)(smem + OFF_VW);
    if (tid < 128)       qp[tid] = g_qproj[b * U_ + u0 + tid];
    else if (tid < 256)  vw[tid - 128] = __ldg(Vw + u0 + tid - 128);

    const int wm = wid & 3;             // t block (rows wm*64..+63)
    const int wn = wid >> 2;            // u block (cols wn*32..+31)
    const int rowA = lane & 15;
    const int ka   = lane >> 4;
    const int rowB = (lane & 7) | ((lane >> 4) << 3);
    const int kb   = (lane >> 3) & 1;
    const uint32_t aOff = (uint32_t)((wm * 64 + rowA) * 128);
    const uint32_t bOff = (uint32_t)(32768 + (wn * 32 + rowB) * 128);
    float* red = (float*)(smem + OFF_RED);

    for (int tile = 0; tile < NT; tile++) {
        float acc[16][4];
#pragma unroll
        for (int i = 0; i < 16; i++)
#pragma unroll
            for (int j = 0; j < 4; j++) acc[i][j] = 0.f;

        for (int c = 0; c < NCH; c++) {
            const int cc  = tile * NCH + c;
            const int s   = cc & 3;
            const int par = (cc >> 2) & 1;
            MBARRIER_WAIT_PARITY(sb + OFF_MBAR + s * 8, par);
            const uint32_t stg = sb + s * STG;
            const uint32_t aB = stg + aOff;
            const uint32_t bB = stg + bOff;
#pragma unroll
            for (int ks = 0; ks < 4; ks++) {
                if (ks >= 2 && c == 16) break;   // loc chunk: K=32 payload only
                const int gA = ks * 2 + ka;
                const int gB = ks * 2 + kb;
                const uint32_t swA = (uint32_t)((gA ^ (rowA & 7)) << 4);
                const uint32_t swB = (uint32_t)((gB ^ (rowB & 7)) << 4);

                uint32_t ah[4][4], bh[4][2], tmp[4];
#pragma unroll
                for (int mt = 0; mt < 4; mt++) ldsm4(ah[mt], aB + mt * 2048 + swA);
                ldsm4(tmp, bB + swB);
                bh[0][0] = tmp[0]; bh[0][1] = tmp[1]; bh[1][0] = tmp[2]; bh[1][1] = tmp[3];
                ldsm4(tmp, bB + 2048 + swB);
                bh[2][0] = tmp[0]; bh[2][1] = tmp[1]; bh[3][0] = tmp[2]; bh[3][1] = tmp[3];
#pragma unroll
                for (int mt = 0; mt < 4; mt++)
#pragma unroll
                    for (int nt = 0; nt < 4; nt++)
                        mma16816(acc[mt * 4 + nt], ah[mt], bh[nt]);
            }
            // this warp is done reading stage s
            if (lane == 0) MBARRIER_ARRIVE(sb + OFF_EMPTY + s * 8);
            // producer: refill stage s once all 16 warps are done with it
            if (tid == 0 && cc + 4 < NCC) {
                MBARRIER_WAIT_PARITY(sb + OFF_EMPTY + s * 8, par);
                issue_cc(sb, cc + 4, b, t00, u0);
            }
        }
        __syncthreads();   // converge warps; order qp/vw/red across tiles

        // epilogue for this tile: s = acc + qp[u]; rowsum += vw[u]*tanh(s)
        const int t0 = t00 + tile * 256;
        float rs[4][2];
#pragma unroll
        for (int mt = 0; mt < 4; mt++) { rs[mt][0] = 0.f; rs[mt][1] = 0.f; }
#pragma unroll
        for (int mt = 0; mt < 4; mt++) {
#pragma unroll
            for (int nt = 0; nt < 4; nt++) {
                int uc = wn * 32 + nt * 8 + ((lane & 3) << 1);
                float q0 = qp[uc], q1 = qp[uc + 1];
                float v0 = vw[uc], v1 = vw[uc + 1];
                float* a = acc[mt * 4 + nt];
                rs[mt][0] += v0 * fast_tanh(a[0] + q0) + v1 * fast_tanh(a[1] + q1);
                rs[mt][1] += v0 * fast_tanh(a[2] + q0) + v1 * fast_tanh(a[3] + q1);
            }
#pragma unroll
            for (int off = 1; off <= 2; off <<= 1) {
                rs[mt][0] += __shfl_xor_sync(0xffffffffu, rs[mt][0], off);
                rs[mt][1] += __shfl_xor_sync(0xffffffffu, rs[mt][1], off);
            }
        }
        if ((lane & 3) == 0) {
#pragma unroll
            for (int mt = 0; mt < 4; mt++) {
                int r = wm * 64 + mt * 16 + (lane >> 2);
                red[wn * 256 + r]     = rs[mt][0];
                red[wn * 256 + r + 8] = rs[mt][1];
            }
        }
        __syncthreads();
        if (tid < 256) {
            float sv = red[tid] + red[256 + tid] + red[512 + tid] + red[768 + tid];
            g_part[(size_t)ut * (B_ * T_) + b * T_ + t0 + tid] = sv;
        }
    }
}

// ---------------- 4) combine + softmax ---------------------------------------
__global__ void softmax_kernel(const float* __restrict__ Vb,
                               float* __restrict__ score,
                               float* __restrict__ att) {
    int b = blockIdx.x;
    int tid = threadIdx.x;  // 256
    __shared__ float sm[256];
    const float vb = __ldg(Vb);

    float v[8];
    float m = -3.402823466e38f;
#pragma unroll
    for (int i = 0; i < 8; i++) {
        int t = tid + i * 256;
        float s = vb;
#pragma unroll
        for (int z = 0; z < 8; z++) s += g_part[(size_t)z * (B_ * T_) + b * T_ + t];
        v[i] = s;
        score[(size_t)b * T_ + t] = s;
        m = fmaxf(m, s);
    }
    sm[tid] = m;
    __syncthreads();
    for (int off = 128; off > 0; off >>= 1) {
        if (tid < off) sm[tid] = fmaxf(sm[tid], sm[tid + off]);
        __syncthreads();
    }
    float M = sm[0];
    __syncthreads();

    float acc = 0.f;
#pragma unroll
    for (int i = 0; i < 8; i++) { v[i] = expf(v[i] - M); acc += v[i]; }
    sm[tid] = acc;
    __syncthreads();
    for (int off = 128; off > 0; off >>= 1) {
        if (tid < off) sm[tid] += sm[tid + off];
        __syncthreads();
    }
    float inv = 1.0f / sm[0];
#pragma unroll
    for (int i = 0; i < 8; i++)
        att[(size_t)b * T_ + tid + i * 256] = v[i] * inv;
}

// ---------------- 5) context (uint4 granule loads from packed fp16) -----------
// grid (b=32, sp=32), 128 threads. Thread = one granule (8 h), 64 t's.
__global__ void ctx_partial_kernel(const float* __restrict__ att) {
    int b   = blockIdx.x;
    int sp  = blockIdx.y;              // 0..31, 64 t each
    int tid = threadIdx.x;             // 0..127: c = tid>>3, gr = tid&7
    int c   = tid >> 3;
    int gr  = tid & 7;
    __shared__ float a[64];
    int t0 = sp * 64;
    if (tid < 64) a[tid] = att[(size_t)b * T_ + t0 + tid];
    __syncthreads();
    const uint4* base = g_vpk + ((size_t)((b * NCH + c) * 2048 + t0) * 8);
    float acc[8];
#pragma unroll
    for (int i = 0; i < 8; i++) acc[i] = 0.f;
#pragma unroll 8
    for (int t = 0; t < 64; t++) {
        uint4 v = base[(size_t)t * 8 + (gr ^ (t & 7))];
        const __half2* h2 = (const __half2*)&v;
        float w = a[t];
#pragma unroll
        for (int j = 0; j < 4; j++) {
            float2 f = __half22float2(h2[j]);
            acc[j * 2]     += w * f.x;
            acc[j * 2 + 1] += w * f.y;
        }
    }
    int h = c * 64 + gr * 8;
    float* out = g_ctx_partial + ((size_t)(b * 32 + sp) * H_) + h;
#pragma unroll
    for (int i = 0; i < 8; i++) out[i] = acc[i];
}

__global__ void ctx_reduce_kernel(float* __restrict__ ctx) {
    int idx = blockIdx.x * 256 + threadIdx.x;   // 0..32767
    int b = idx >> 10;
    int h = idx & (H_ - 1);
    float s = 0.f;
#pragma unroll
    for (int sp = 0; sp < 32; sp++)
        s += g_ctx_partial[((size_t)(b * 32 + sp)) * H_ + h];
    ctx[idx] = s;
}

// ---------------- launch ------------------------------------------------------
extern "C" void kernel_launch(void* const* d_in, const int* in_sizes, int n_in,
                              void* d_out, int out_size) {
    const float* query    = (const float*)d_in[0];
    const float* values   = (const float*)d_in[1];
    const float* prev_att = (const float*)d_in[2];
    const float* W1w      = (const float*)d_in[3];
    const float* W1b      = (const float*)d_in[4];
    const float* W2w      = (const float*)d_in[5];
    const float* W2b      = (const float*)d_in[6];
    const float* Vw       = (const float*)d_in[7];
    const float* Vb       = (const float*)d_in[8];
    const float* conv_w   = (const float*)d_in[9];
    const float* LPw      = (const float*)d_in[10];

    float* out   = (float*)d_out;
    float* ctx   = out;
    float* att   = out + B_ * H_;
    float* score = out + B_ * H_ + B_ * T_;

    cudaFuncSetAttribute(score_mma_kernel,
                         cudaFuncAttributeMaxDynamicSharedMemorySize, SMEM_TOTAL);
    cudaFuncSetAttribute(qproj_kernel,
                         cudaFuncAttributeMaxDynamicSharedMemorySize, B_ * H_ * 4);

    qproj_kernel<<<U_ / 8, 256, B_ * H_ * 4>>>(query, W2w, W1b, W2b);
    pack_w_kernel<<<(16 * U_) / 256, 256>>>(W1w);
    pack_lp_kernel<<<U_ / 256, 256>>>(LPw);
    pack_values_kernel<<<(B_ * 16 * T_ * 8) / 256, 256>>>(values);
    {
        dim3 g(T_ / 256, B_);
        loc_pack_kernel<<<g, 256>>>(prev_att, conv_w);
    }
    {
        dim3 g(8, B_, 2);   // x = u-tile (fastest), y = b, z = t-megatile (4 tiles each)
        score_mma_kernel<<<g, 512, SMEM_TOTAL>>>(Vw);
    }
    softmax_kernel<<<B_, 256>>>(Vb, score, att);
    {
        dim3 g(B_, 32);
        ctx_partial_kernel<<<g, 128>>>(att);
        ctx_reduce_kernel<<<B_ * H_ / 256, 256>>>(ctx);
    }
}

// round 13
// speedup vs baseline: 1.0950x; 1.0950x over previous
#include <cuda_runtime.h>
#include <cuda_fp16.h>
#include <cstdint>
#include <math.h>

// ----------------------------------------------------------------------------
// BahdanauAttentionAudio — HMMA fp16 single-term score GEMM (NT=2 persistent)
//   B=32, T=2048, H=1024, U=1024, KN=32
// Output layout: [ ctx (32*1024) | att (32*2048) | score (32*2048) ]
// ----------------------------------------------------------------------------

#define B_   32
#define T_   2048
#define H_   1024
#define U_   1024
#define KN_  32
#define TAPS 31
#define NCH  17            // 16 chunks of H (K=64) + 1 loc chunk (K=32, zero-padded)
#define NT   2             // t-tiles per score CTA
#define NCC  (NT * NCH)    // 34 continuous chunks per CTA

// packed format: per (chunk c, row r): 128 bytes = 64 fp16 (k = c*64 .. +63)
// granule g (8 fp16 = 16B) stored at byte offset ((g ^ (r & 7)) * 16)
__device__ __align__(128) uint4 g_vpk[(size_t)B_ * NCH * T_ * 8];   // [b][c][t][8]
__device__ __align__(128) uint4 g_wpk[(size_t)NCH * U_ * 8];        // [c][u][8]
__device__ __align__(16)  float g_qproj[B_ * U_];
__device__ __align__(16)  float g_part[8 * B_ * T_];
__device__ __align__(16)  float g_ctx_partial[B_ * 32 * H_];

// ---------------- helpers ----------------------------------------------------
__device__ __forceinline__ uint32_t smem_to_u32(const void* p) {
    uint32_t a;
    asm("{ .reg .u64 t; cvta.to.shared.u64 t, %1; cvt.u32.u64 %0, t; }"
        : "=r"(a) : "l"(p));
    return a;
}

__device__ __forceinline__ uint32_t pkh(float a, float b) {
    __half2 h = __floats2half2_rn(a, b);
    return *reinterpret_cast<uint32_t*>(&h);
}

__device__ __forceinline__ uint4 pk8(const float* f) {
    uint4 r;
    r.x = pkh(f[0], f[1]); r.y = pkh(f[2], f[3]);
    r.z = pkh(f[4], f[5]); r.w = pkh(f[6], f[7]);
    return r;
}

__device__ __forceinline__ float fast_tanh(float x) {
    float xx = fminf(fmaxf(x, -15.f), 15.f) * 2.8853900817779268f;
    float e, r;
    asm("ex2.approx.f32 %0, %1;" : "=f"(e) : "f"(xx));
    float d = e + 1.f;
    asm("rcp.approx.f32 %0, %1;" : "=f"(r) : "f"(d));
    return (e - 1.f) * r;
}

#define MBARRIER_INIT(m, c) \
    asm volatile("mbarrier.init.shared.b64 [%0], %1;" \
                 :: "r"((uint32_t)(m)), "r"((uint32_t)(c)) : "memory")
#define MBARRIER_EXPECT_TX(m, n) \
    asm volatile("mbarrier.arrive.expect_tx.shared.b64 _, [%0], %1;" \
                 :: "r"((uint32_t)(m)), "r"((uint32_t)(n)) : "memory")
#define MBARRIER_ARRIVE(m) \
    asm volatile("mbarrier.arrive.shared.b64 _, [%0];" \
                 :: "r"((uint32_t)(m)) : "memory")

#define MBARRIER_WAIT_PARITY(mb, pp) do {                                     \
    uint32_t _m = (uint32_t)(mb), _p = (uint32_t)(pp), _d;                    \
    asm volatile(                                                             \
        "{\n\t.reg .pred p;\n\t"                                              \
        "mbarrier.try_wait.parity.acquire.cta.shared::cta.b64 p, [%1], %2;\n\t" \
        "selp.b32 %0, 1, 0, p;\n\t}"                                          \
        : "=r"(_d) : "r"(_m), "r"(_p) : "memory");                            \
    if (!_d) {                                                                \
        asm volatile(                                                         \
            "{\n\t.reg .pred P1;\n\t"                                         \
            "WL_%=:\n\t"                                                      \
            "mbarrier.try_wait.parity.acquire.cta.shared::cta.b64 P1, [%0], %1, 0x989680;\n\t" \
            "@P1 bra.uni WD_%=;\n\t"                                          \
            "bra.uni WL_%=;\n\t"                                              \
            "WD_%=:\n\t}"                                                     \
            :: "r"(_m), "r"(_p) : "memory");                                  \
    }                                                                         \
} while (0)

__device__ __forceinline__ void bulk_g2s(uint32_t dst, const void* src,
                                         uint32_t bytes, uint32_t mbar) {
    asm volatile(
        "cp.async.bulk.shared::cluster.global.mbarrier::complete_tx::bytes "
        "[%0], [%1], %2, [%3];"
        :: "r"(dst), "l"(src), "r"(bytes), "r"(mbar) : "memory");
}

__device__ __forceinline__ void ldsm4(uint32_t (&r)[4], uint32_t a) {
    asm volatile("ldmatrix.sync.aligned.m8n8.x4.shared.b16 {%0,%1,%2,%3}, [%4];"
                 : "=r"(r[0]), "=r"(r[1]), "=r"(r[2]), "=r"(r[3]) : "r"(a));
}

__device__ __forceinline__ void mma16816(float* c, const uint32_t* a,
                                         const uint32_t* b) {
    asm volatile(
        "mma.sync.aligned.m16n8k16.row.col.f32.f16.f16.f32 "
        "{%0,%1,%2,%3}, {%4,%5,%6,%7}, {%8,%9}, {%0,%1,%2,%3};"
        : "+f"(c[0]), "+f"(c[1]), "+f"(c[2]), "+f"(c[3])
        : "r"(a[0]), "r"(a[1]), "r"(a[2]), "r"(a[3]), "r"(b[0]), "r"(b[1]));
}

// ---------------- 1) query projection ----------------------------------------
__global__ void qproj_kernel(const float* __restrict__ query,
                             const float* __restrict__ W2w,
                             const float* __restrict__ W1b,
                             const float* __restrict__ W2b) {
    extern __shared__ float qs[];      // [32][1024]
    const int tid  = threadIdx.x;      // 256
    const int lane = tid & 31;
    const int wid  = tid >> 5;
    for (int i = tid; i < B_ * H_ / 4; i += 256)
        ((float4*)qs)[i] = ((const float4*)query)[i];
    __syncthreads();

    const int u = blockIdx.x * 8 + wid;
    const float* wrow = W2w + (size_t)u * H_;
    float w[32];
#pragma unroll
    for (int j = 0; j < 32; j++) w[j] = __ldg(&wrow[j * 32 + lane]);

    float bias = 0.f;
    if (lane == 0) bias = __ldg(&W1b[u]) + __ldg(&W2b[u]);

    for (int b = 0; b < B_; b++) {
        const float* qr = qs + b * H_;
        float acc = 0.f;
#pragma unroll
        for (int j = 0; j < 32; j++) acc += w[j] * qr[j * 32 + lane];
#pragma unroll
        for (int off = 16; off > 0; off >>= 1)
            acc += __shfl_xor_sync(0xffffffffu, acc, off);
        if (lane == 0) g_qproj[(size_t)b * U_ + u] = acc + bias;
    }
}

// ---------------- 2a) pack values (fp16, coalesced granule-per-thread) -------
__global__ void pack_values_kernel(const float* __restrict__ values) {
    int idx = blockIdx.x * 256 + threadIdx.x;
    int g = idx & 7;
    int t = (idx >> 3) & 2047;
    int c = (idx >> 14) & 15;
    int b = idx >> 18;
    const float4* src = (const float4*)(values +
        ((size_t)(b * 2048 + t) * 1024 + c * 64 + g * 8));
    float4 v0 = __ldg(src), v1 = __ldg(src + 1);
    float f[8] = {v0.x, v0.y, v0.z, v0.w, v1.x, v1.y, v1.z, v1.w};
    g_vpk[((size_t)((b * NCH + c) * 2048 + t) * 8) + (g ^ (t & 7))] = pk8(f);
}

// ---------------- 2b) pack W1_w (fp16) ----------------------------------------
__global__ void pack_w_kernel(const float* __restrict__ W1w) {
    int idx = blockIdx.x * 256 + threadIdx.x;   // c*1024 + u  (c 0..15)
    int u = idx & 1023;
    int c = idx >> 10;
    const float4* src = (const float4*)(W1w + ((size_t)u * 1024 + c * 64));
    uint4* dst = g_wpk + ((size_t)(c * U_ + u) * 8);
    int r = u & 7;
    float f[8];
#pragma unroll
    for (int g = 0; g < 8; g++) {
        float4 v0 = __ldg(src + g * 2), v1 = __ldg(src + g * 2 + 1);
        f[0] = v0.x; f[1] = v0.y; f[2] = v0.z; f[3] = v0.w;
        f[4] = v1.x; f[5] = v1.y; f[6] = v1.z; f[7] = v1.w;
        dst[g ^ r] = pk8(f);
    }
}

// ---------------- 2c) pack loc_proj_w (chunk 16 of W) -------------------------
__global__ void pack_lp_kernel(const float* __restrict__ LPw) {
    int u = blockIdx.x * 256 + threadIdx.x;     // 0..1023
    const float4* src = (const float4*)(LPw + (size_t)u * 32);
    uint4* dst = g_wpk + ((size_t)(16 * U_ + u) * 8);
    int r = u & 7;
    float f[8];
    uint4 z = make_uint4(0, 0, 0, 0);
#pragma unroll
    for (int g = 0; g < 4; g++) {
        float4 v0 = __ldg(src + g * 2), v1 = __ldg(src + g * 2 + 1);
        f[0] = v0.x; f[1] = v0.y; f[2] = v0.z; f[3] = v0.w;
        f[4] = v1.x; f[5] = v1.y; f[6] = v1.z; f[7] = v1.w;
        dst[g ^ r] = pk8(f);
    }
#pragma unroll
    for (int g = 4; g < 8; g++) dst[g ^ r] = z;
}

// ---------------- 2d) location conv + pack (chunk 16 of V) --------------------
__global__ void loc_pack_kernel(const float* __restrict__ prev_att,
                                const float* __restrict__ conv_w) {
    int b  = blockIdx.y;
    int t0 = blockIdx.x * 256;
    int tid = threadIdx.x;
    __shared__ float pa[256 + TAPS - 1];
    __shared__ float w[KN_][TAPS];
    for (int i = tid; i < 256 + TAPS - 1; i += 256) {
        int t = t0 - (TAPS / 2) + i;
        pa[i] = (t >= 0 && t < T_) ? prev_att[(size_t)b * T_ + t] : 0.f;
    }
    for (int i = tid; i < KN_ * TAPS; i += 256) w[i / TAPS][i % TAPS] = conv_w[i];
    __syncthreads();
    int t = t0 + tid;
    float a[KN_];
#pragma unroll 4
    for (int k = 0; k < KN_; k++) {
        float s = 0.f;
#pragma unroll
        for (int j = 0; j < TAPS; j++) s += w[k][j] * pa[tid + j];
        a[k] = s;
    }
    uint4* dst = g_vpk + ((size_t)((b * NCH + 16) * 2048 + t) * 8);
    int r = t & 7;
    uint4 z = make_uint4(0, 0, 0, 0);
#pragma unroll
    for (int g = 0; g < 4; g++) dst[g ^ r] = pk8(a + g * 8);
#pragma unroll
    for (int g = 4; g < 8; g++) dst[g ^ r] = z;
}

// ---------------- 3) score GEMM via mma.sync (NT=2 persistent) ----------------
// CTA: 256 t x 128 u tile, 512 threads, NT=2 tiles per CTA (t0 advances).
// Continuous chunk stream cc = 0..33 through a 4-stage 48KB pipeline; the
// producer runs ahead across the tile boundary so the tile-0 epilogue overlaps
// with TMA prefetch of tile 1.
#define STG       49152
#define OFF_MBAR  196608     // 4 x full (TMA) barriers, 8B each
#define OFF_EMPTY 196640     // 4 x empty barriers, 8B each
#define OFF_QP    196672
#define OFF_VW    197184
#define OFF_RED   197696
#define SMEM_TOTAL 201792

__device__ __forceinline__ void issue_cc(uint32_t sb, int cc,
                                         int b, int t00, int u0) {
    const int s    = cc & 3;
    const int tile = cc / NCH;
    const int c    = cc - tile * NCH;
    uint32_t mbar = sb + OFF_MBAR + s * 8;
    MBARRIER_EXPECT_TX(mbar, 49152u);
    bulk_g2s(sb + s * STG,
             (const void*)(g_vpk + ((size_t)((b * NCH + c) * 2048 + t00 + tile * 256) * 8)),
             32768u, mbar);
    bulk_g2s(sb + s * STG + 32768,
             (const void*)(g_wpk + ((size_t)(c * U_ + u0) * 8)),
             16384u, mbar);
}

__global__ __launch_bounds__(512, 1)
void score_mma_kernel(const float* __restrict__ Vw) {
    extern __shared__ char smem[];
    const uint32_t sb = smem_to_u32(smem);
    const int tid  = threadIdx.x;
    const int lane = tid & 31;
    const int wid  = tid >> 5;
    const int ut  = blockIdx.x;         // 0..7 (fastest -> A L2 reuse)
    const int b   = blockIdx.y;         // 0..31
    const int tt2 = blockIdx.z;         // 0..3
    const int t00 = tt2 * 512, u0 = ut * 128;

    if (tid == 0) {
#pragma unroll
        for (int s = 0; s < 4; s++) {
            MBARRIER_INIT(sb + OFF_MBAR + s * 8, 1);
            MBARRIER_INIT(sb + OFF_EMPTY + s * 8, 16);   // one arrive per warp
        }
    }
    __syncthreads();
    if (tid == 0) {
        for (int cc = 0; cc < 4; cc++) issue_cc(sb, cc, b, t00, u0);
    }

    float* qp = (float*)(smem + OFF_QP);
    float* vw = (float*)(smem + OFF_VW);
    if (tid < 128)       qp[tid] = g_qproj[b * U_ + u0 + tid];
    else if (tid < 256)  vw[tid - 128] = __ldg(Vw + u0 + tid - 128);

    const int wm = wid & 3;             // t block (rows wm*64..+63)
    const int wn = wid >> 2;            // u block (cols wn*32..+31)
    const int rowA = lane & 15;
    const int ka   = lane >> 4;
    const int rowB = (lane & 7) | ((lane >> 4) << 3);
    const int kb   = (lane >> 3) & 1;
    const uint32_t aOff = (uint32_t)((wm * 64 + rowA) * 128);
    const uint32_t bOff = (uint32_t)(32768 + (wn * 32 + rowB) * 128);
    float* red = (float*)(smem + OFF_RED);

    for (int tile = 0; tile < NT; tile++) {
        float acc[16][4];
#pragma unroll
        for (int i = 0; i < 16; i++)
#pragma unroll
            for (int j = 0; j < 4; j++) acc[i][j] = 0.f;

        for (int c = 0; c < NCH; c++) {
            const int cc  = tile * NCH + c;
            const int s   = cc & 3;
            const int par = (cc >> 2) & 1;
            MBARRIER_WAIT_PARITY(sb + OFF_MBAR + s * 8, par);
            const uint32_t stg = sb + s * STG;
            const uint32_t aB = stg + aOff;
            const uint32_t bB = stg + bOff;
#pragma unroll
            for (int ks = 0; ks < 4; ks++) {
                if (ks >= 2 && c == 16) break;   // loc chunk: K=32 payload only
                const int gA = ks * 2 + ka;
                const int gB = ks * 2 + kb;
                const uint32_t swA = (uint32_t)((gA ^ (rowA & 7)) << 4);
                const uint32_t swB = (uint32_t)((gB ^ (rowB & 7)) << 4);

                uint32_t ah[4][4], bh[4][2], tmp[4];
#pragma unroll
                for (int mt = 0; mt < 4; mt++) ldsm4(ah[mt], aB + mt * 2048 + swA);
                ldsm4(tmp, bB + swB);
                bh[0][0] = tmp[0]; bh[0][1] = tmp[1]; bh[1][0] = tmp[2]; bh[1][1] = tmp[3];
                ldsm4(tmp, bB + 2048 + swB);
                bh[2][0] = tmp[0]; bh[2][1] = tmp[1]; bh[3][0] = tmp[2]; bh[3][1] = tmp[3];
#pragma unroll
                for (int mt = 0; mt < 4; mt++)
#pragma unroll
                    for (int nt = 0; nt < 4; nt++)
                        mma16816(acc[mt * 4 + nt], ah[mt], bh[nt]);
            }
            // this warp is done reading stage s
            if (lane == 0) MBARRIER_ARRIVE(sb + OFF_EMPTY + s * 8);
            // producer: refill stage s once all 16 warps are done with it
            if (tid == 0 && cc + 4 < NCC) {
                MBARRIER_WAIT_PARITY(sb + OFF_EMPTY + s * 8, par);
                issue_cc(sb, cc + 4, b, t00, u0);
            }
        }
        __syncthreads();   // converge warps; order qp/vw/red across tiles

        // epilogue for this tile: s = acc + qp[u]; rowsum += vw[u]*tanh(s)
        const int t0 = t00 + tile * 256;
        float rs[4][2];
#pragma unroll
        for (int mt = 0; mt < 4; mt++) { rs[mt][0] = 0.f; rs[mt][1] = 0.f; }
#pragma unroll
        for (int mt = 0; mt < 4; mt++) {
#pragma unroll
            for (int nt = 0; nt < 4; nt++) {
                int uc = wn * 32 + nt * 8 + ((lane & 3) << 1);
                float q0 = qp[uc], q1 = qp[uc + 1];
                float v0 = vw[uc], v1 = vw[uc + 1];
                float* a = acc[mt * 4 + nt];
                rs[mt][0] += v0 * fast_tanh(a[0] + q0) + v1 * fast_tanh(a[1] + q1);
                rs[mt][1] += v0 * fast_tanh(a[2] + q0) + v1 * fast_tanh(a[3] + q1);
            }
#pragma unroll
            for (int off = 1; off <= 2; off <<= 1) {
                rs[mt][0] += __shfl_xor_sync(0xffffffffu, rs[mt][0], off);
                rs[mt][1] += __shfl_xor_sync(0xffffffffu, rs[mt][1], off);
            }
        }
        if ((lane & 3) == 0) {
#pragma unroll
            for (int mt = 0; mt < 4; mt++) {
                int r = wm * 64 + mt * 16 + (lane >> 2);
                red[wn * 256 + r]     = rs[mt][0];
                red[wn * 256 + r + 8] = rs[mt][1];
            }
        }
        __syncthreads();
        if (tid < 256) {
            float sv = red[tid] + red[256 + tid] + red[512 + tid] + red[768 + tid];
            g_part[(size_t)ut * (B_ * T_) + b * T_ + t0 + tid] = sv;
        }
    }
}

// ---------------- 4) combine + softmax ---------------------------------------
__global__ void softmax_kernel(const float* __restrict__ Vb,
                               float* __restrict__ score,
                               float* __restrict__ att) {
    int b = blockIdx.x;
    int tid = threadIdx.x;  // 256
    __shared__ float sm[256];
    const float vb = __ldg(Vb);

    float v[8];
    float m = -3.402823466e38f;
#pragma unroll
    for (int i = 0; i < 8; i++) {
        int t = tid + i * 256;
        float s = vb;
#pragma unroll
        for (int z = 0; z < 8; z++) s += g_part[(size_t)z * (B_ * T_) + b * T_ + t];
        v[i] = s;
        score[(size_t)b * T_ + t] = s;
        m = fmaxf(m, s);
    }
    sm[tid] = m;
    __syncthreads();
    for (int off = 128; off > 0; off >>= 1) {
        if (tid < off) sm[tid] = fmaxf(sm[tid], sm[tid + off]);
        __syncthreads();
    }
    float M = sm[0];
    __syncthreads();

    float acc = 0.f;
#pragma unroll
    for (int i = 0; i < 8; i++) { v[i] = expf(v[i] - M); acc += v[i]; }
    sm[tid] = acc;
    __syncthreads();
    for (int off = 128; off > 0; off >>= 1) {
        if (tid < off) sm[tid] += sm[tid + off];
        __syncthreads();
    }
    float inv = 1.0f / sm[0];
#pragma unroll
    for (int i = 0; i < 8; i++)
        att[(size_t)b * T_ + tid + i * 256] = v[i] * inv;
}

// ---------------- 5) context (uint4 granule loads from packed fp16) -----------
// grid (b=32, sp=32), 128 threads. Thread = one granule (8 h), 64 t's.
__global__ void ctx_partial_kernel(const float* __restrict__ att) {
    int b   = blockIdx.x;
    int sp  = blockIdx.y;              // 0..31, 64 t each
    int tid = threadIdx.x;             // 0..127: c = tid>>3, gr = tid&7
    int c   = tid >> 3;
    int gr  = tid & 7;
    __shared__ float a[64];
    int t0 = sp * 64;
    if (tid < 64) a[tid] = att[(size_t)b * T_ + t0 + tid];
    __syncthreads();
    const uint4* base = g_vpk + ((size_t)((b * NCH + c) * 2048 + t0) * 8);
    float acc[8];
#pragma unroll
    for (int i = 0; i < 8; i++) acc[i] = 0.f;
#pragma unroll 8
    for (int t = 0; t < 64; t++) {
        uint4 v = base[(size_t)t * 8 + (gr ^ (t & 7))];
        const __half2* h2 = (const __half2*)&v;
        float w = a[t];
#pragma unroll
        for (int j = 0; j < 4; j++) {
            float2 f = __half22float2(h2[j]);
            acc[j * 2]     += w * f.x;
            acc[j * 2 + 1] += w * f.y;
        }
    }
    int h = c * 64 + gr * 8;
    float* out = g_ctx_partial + ((size_t)(b * 32 + sp) * H_) + h;
#pragma unroll
    for (int i = 0; i < 8; i++) out[i] = acc[i];
}

__global__ void ctx_reduce_kernel(float* __restrict__ ctx) {
    int idx = blockIdx.x * 256 + threadIdx.x;   // 0..32767
    int b = idx >> 10;
    int h = idx & (H_ - 1);
    float s = 0.f;
#pragma unroll
    for (int sp = 0; sp < 32; sp++)
        s += g_ctx_partial[((size_t)(b * 32 + sp)) * H_ + h];
    ctx[idx] = s;
}

// ---------------- launch ------------------------------------------------------
extern "C" void kernel_launch(void* const* d_in, const int* in_sizes, int n_in,
                              void* d_out, int out_size) {
    const float* query    = (const float*)d_in[0];
    const float* values   = (const float*)d_in[1];
    const float* prev_att = (const float*)d_in[2];
    const float* W1w      = (const float*)d_in[3];
    const float* W1b      = (const float*)d_in[4];
    const float* W2w      = (const float*)d_in[5];
    const float* W2b      = (const float*)d_in[6];
    const float* Vw       = (const float*)d_in[7];
    const float* Vb       = (const float*)d_in[8];
    const float* conv_w   = (const float*)d_in[9];
    const float* LPw      = (const float*)d_in[10];

    float* out   = (float*)d_out;
    float* ctx   = out;
    float* att   = out + B_ * H_;
    float* score = out + B_ * H_ + B_ * T_;

    cudaFuncSetAttribute(score_mma_kernel,
                         cudaFuncAttributeMaxDynamicSharedMemorySize, SMEM_TOTAL);
    cudaFuncSetAttribute(qproj_kernel,
                         cudaFuncAttributeMaxDynamicSharedMemorySize, B_ * H_ * 4);

    qproj_kernel<<<U_ / 8, 256, B_ * H_ * 4>>>(query, W2w, W1b, W2b);
    pack_w_kernel<<<(16 * U_) / 256, 256>>>(W1w);
    pack_lp_kernel<<<U_ / 256, 256>>>(LPw);
    pack_values_kernel<<<(B_ * 16 * T_ * 8) / 256, 256>>>(values);
    {
        dim3 g(T_ / 256, B_);
        loc_pack_kernel<<<g, 256>>>(prev_att, conv_w);
    }
    {
        dim3 g(8, B_, 4);   // x = u-tile (fastest), y = b, z = t-megatile (2 tiles each)
        score_mma_kernel<<<g, 512, SMEM_TOTAL>>>(Vw);
    }
    softmax_kernel<<<B_, 256>>>(Vb, score, att);
    {
        dim3 g(B_, 32);
        ctx_partial_kernel<<<g, 128>>>(att);
        ctx_reduce_kernel<<<B_ * H_ / 256, 256>>>(ctx);
    }
}